// round 1
// baseline (speedup 1.0000x reference)
#include <cuda_runtime.h>

// TranslateCube: out(y,x) = bilinear sample of in at (y - ty, x - tx), zero fill.
// Shapes: images [B*T, 256, 256] fp32, dx/dy [B*T] fp32 (per-image constant shift).

#define HH 256
#define WW 256
#define ROWS_PER_BLOCK 8

__global__ __launch_bounds__(256) void translate_kernel(
    const float* __restrict__ img,
    const float* __restrict__ dx,
    const float* __restrict__ dy,
    float* __restrict__ out)
{
    const int imgIdx = blockIdx.y;
    const int yBase  = blockIdx.x * ROWS_PER_BLOCK;
    const float tx = __ldg(dx + imgIdx);
    const float ty = __ldg(dy + imgIdx);

    const int x = threadIdx.x;
    // Per-column source coordinate (constant across rows for this thread)
    const float sx  = (float)x - tx;
    const float x0f = floorf(sx);
    const float wx  = sx - x0f;
    const int   x0  = (int)x0f;
    const bool  vx0 = (x0 >= 0)     && (x0 <= WW - 1);
    const bool  vx1 = (x0 + 1 >= 0) && (x0 + 1 <= WW - 1);

    const float* base  = img + (size_t)imgIdx * (HH * WW);
    float*       obase = out + (size_t)imgIdx * (HH * WW);

    #pragma unroll
    for (int r = 0; r < ROWS_PER_BLOCK; ++r) {
        const int y = yBase + r;
        const float sy  = (float)y - ty;
        const float y0f = floorf(sy);
        const float wy  = sy - y0f;
        const int   y0  = (int)y0f;
        const bool  vy0 = (y0 >= 0)     && (y0 <= HH - 1);
        const bool  vy1 = (y0 + 1 >= 0) && (y0 + 1 <= HH - 1);

        const float* row0 = base + (size_t)y0 * WW;
        const float* row1 = row0 + WW;

        const float c00 = (vy0 && vx0) ? __ldg(row0 + x0)     : 0.0f;
        const float c01 = (vy0 && vx1) ? __ldg(row0 + x0 + 1) : 0.0f;
        const float c10 = (vy1 && vx0) ? __ldg(row1 + x0)     : 0.0f;
        const float c11 = (vy1 && vx1) ? __ldg(row1 + x0 + 1) : 0.0f;

        // (1-wx)*c00 + wx*c01  ==  c00 + wx*(c01-c00)
        const float top = fmaf(wx, c01 - c00, c00);
        const float bot = fmaf(wx, c11 - c10, c10);
        obase[(size_t)y * WW + x] = fmaf(wy, bot - top, top);
    }
}

extern "C" void kernel_launch(void* const* d_in, const int* in_sizes, int n_in,
                              void* d_out, int out_size) {
    const float* images = (const float*)d_in[0];
    const float* dx     = (const float*)d_in[1];
    const float* dy     = (const float*)d_in[2];
    // d_in[3] is winsize (unused by the math)
    float* out = (float*)d_out;

    const int n_images = in_sizes[1];  // B*T (dx element count)

    dim3 grid(HH / ROWS_PER_BLOCK, n_images);
    translate_kernel<<<grid, 256>>>(images, dx, dy, out);
}